// round 14
// baseline (speedup 1.0000x reference)
#include <cuda_runtime.h>
#include <cstdint>

#define BATCH   8
#define NPTS    8192
#define DIM     64
#define SPTS    1024      // NPOINT
#define NS      32        // NSAMPLE
#define MROWS   (BATCH*SPTS*NS)   // 262144
#define NBLK    (MROWS/64)        // 4096 gemm blocks

typedef unsigned long long u64;

// ---------------- f32x2 packed helpers --------------------------------------
__device__ __forceinline__ u64 pack2(float lo, float hi){
  u64 r; asm("mov.b64 %0,{%1,%2};" : "=l"(r) : "f"(lo), "f"(hi)); return r;
}
__device__ __forceinline__ void unpack2(float& lo, float& hi, u64 p){
  asm("mov.b64 {%0,%1},%2;" : "=f"(lo), "=f"(hi) : "l"(p));
}
__device__ __forceinline__ u64 add2(u64 a, u64 b){
  u64 r; asm("add.rn.f32x2 %0,%1,%2;" : "=l"(r) : "l"(a), "l"(b)); return r;
}
__device__ __forceinline__ u64 mul2(u64 a, u64 b){
  u64 r; asm("mul.rn.f32x2 %0,%1,%2;" : "=l"(r) : "l"(a), "l"(b)); return r;
}
__device__ __forceinline__ void fma2(u64& d, u64 a, u64 b){
  asm("fma.rn.f32x2 %0,%1,%2,%0;" : "+l"(d) : "l"(a), "l"(b));
}

// ---------------- scratch ---------------------------------------------------
__device__ int   g_fps_idx[BATCH*SPTS];
__device__ float g_new_xyz[BATCH*SPTS*3];
__device__ int   g_ball[BATCH*SPTS*NS];
__device__ float g_ptsT[BATCH*NPTS*DIM];
__device__ float g_h1[(size_t)MROWS*64];
__device__ float g_h2[(size_t)MROWS*64];
__device__ float g_mx[(size_t)BATCH*SPTS*128];
__device__ float g_mn[(size_t)BATCH*SPTS*128];
__device__ float g_pS [(size_t)128*NBLK];   // channel-major
__device__ float g_pSS[(size_t)128*NBLK];
__device__ float g_scale[128];
__device__ float g_shift[128];

// ---------------- FPS: byte-identical to R11 (proven 1043) ------------------
__global__ __launch_bounds__(1024,1) void fps_kernel(const float* __restrict__ xyz){
  extern __shared__ float sxyz[];            // 3*8192 floats
  __shared__ unsigned swarp[32];
  __shared__ unsigned srev[2];
  const int b   = blockIdx.x;
  const int tid = threadIdx.x;
  const float* xb = xyz + (size_t)b*3*NPTS;
  for (int i=tid; i<3*NPTS; i+=1024) sxyz[i]=xb[i];
  if (tid<2) srev[tid]=0u;
  __syncthreads();

  u64 rx2[4], ry2[4], rz2[4];
  float rdl[4], rdh[4];
#pragma unroll
  for (int j=0;j<4;j++){
    int plo=j*1024+tid, phi=(j+4)*1024+tid;
    rx2[j]=pack2(sxyz[plo],       sxyz[phi]);
    ry2[j]=pack2(sxyz[NPTS+plo],  sxyz[NPTS+phi]);
    rz2[j]=pack2(sxyz[2*NPTS+plo],sxyz[2*NPTS+phi]);
    rdl[j]=1e10f; rdh[j]=1e10f;
  }
  int far=0, p=0;
  const int lane=tid&31, wid=tid>>5;
  const unsigned base = (unsigned)(NPTS-1-tid);

  for (int it=0; it<SPTS; ++it){
    if (tid==0) g_fps_idx[b*SPTS+it]=far;
    const float cx=sxyz[far], cy=sxyz[NPTS+far], cz=sxyz[2*NPTS+far];
    const u64 ncx=pack2(-cx,-cx), ncy=pack2(-cy,-cy), ncz=pack2(-cz,-cz);
    float m=0.f;
#pragma unroll
    for (int j=0;j<4;j++){
      u64 dx=add2(rx2[j],ncx);            // x + (-c) == x - c (IEEE)
      u64 dy=add2(ry2[j],ncy);
      u64 dz=add2(rz2[j],ncz);
      u64 s2=add2(add2(mul2(dx,dx),mul2(dy,dy)),mul2(dz,dz));
      float dl,dh; unpack2(dl,dh,s2);
      float nl=fminf(rdl[j],dl), nh=fminf(rdh[j],dh);
      rdl[j]=nl; rdh[j]=nh;
      m = fmaxf(m, fmaxf(nl,nh));
    }
    const unsigned wbits = __reduce_max_sync(0xffffffffu, __float_as_uint(m));
    if (lane==0) swarp[wid]=wbits;
    __syncthreads();                       // (1) warp maxima ready
    const unsigned vbits = __reduce_max_sync(0xffffffffu, swarp[lane]);
    const float vmax = __uint_as_float(vbits);
    if (wbits==vbits){                     // WARP-UNIFORM guard
      unsigned rev=0u;
#pragma unroll
      for (int j=0;j<4;j++){
        if (rdl[j]==vmax){ unsigned r=base-(unsigned)(j<<10);     rev = r>rev?r:rev; }
        if (rdh[j]==vmax){ unsigned r=base-(unsigned)((j+4)<<10); rev = r>rev?r:rev; }
      }
      rev = __reduce_max_sync(0xffffffffu, rev);
      if (lane==0) atomicMax(&srev[p], rev);
    }
    __syncthreads();                       // (2) index ready
    far = (NPTS-1) - (int)srev[p];
    if (tid==0) srev[p^1]=0u;
    p ^= 1;
  }
}

// ---------------- new_xyz gather + first output section --------------------
__global__ void newxyz_kernel(const float* __restrict__ xyz, float* __restrict__ out){
  int b=blockIdx.x, s=threadIdx.x;
  int idx = g_fps_idx[b*SPTS+s];
#pragma unroll
  for (int d=0; d<3; d++){
    float v = xyz[(size_t)b*3*NPTS + (size_t)d*NPTS + idx];
    g_new_xyz[(b*SPTS+s)*3+d]=v;
    out[(size_t)b*3*SPTS + (size_t)d*SPTS + s]=v;
  }
}

// ---------------- ball query: one warp per query ---------------------------
__global__ void ball_kernel(const float* __restrict__ xyz){
  const int gw   = (blockIdx.x*blockDim.x + threadIdx.x) >> 5;  // 0..8191
  const int lane = threadIdx.x & 31;
  const int wl   = threadIdx.x >> 5;
  const int b = gw >> 10;
  __shared__ int sidx[8][NS];
  const float cx=g_new_xyz[gw*3+0], cy=g_new_xyz[gw*3+1], cz=g_new_xyz[gw*3+2];
  const float* xb = xyz + (size_t)b*3*NPTS;
  unsigned cnt=0;
  for (int basep=0; basep<NPTS; basep+=32){
    int pp = basep+lane;
    float dx=__fsub_rn(cx,xb[pp]);
    float dy=__fsub_rn(cy,xb[NPTS+pp]);
    float dz=__fsub_rn(cz,xb[2*NPTS+pp]);
    float d=__fadd_rn(__fadd_rn(__fmul_rn(dx,dx),__fmul_rn(dy,dy)),__fmul_rn(dz,dz));
    bool in = !(d > 0.04f);
    unsigned mm = __ballot_sync(0xffffffffu, in);
    if (in){
      unsigned r = cnt + __popc(mm & ((1u<<lane)-1u));
      if (r < NS) sidx[wl][r] = pp;
    }
    cnt += __popc(mm);
    if (cnt >= NS) break;
  }
  __syncwarp();
  unsigned c = cnt < NS ? cnt : NS;
  int first = sidx[wl][0];
  int v = (lane < (int)c) ? sidx[wl][lane] : first;
  g_ball[gw*NS + lane] = v;
}

// ---------------- points transpose (B,64,N) -> (B,N,64) --------------------
__global__ void transpose_kernel(const float* __restrict__ pts){
  __shared__ float tile[32][33];
  int b  = blockIdx.z;
  int n0 = blockIdx.x*32;
  int c0 = blockIdx.y*32;
  int tx = threadIdx.x, ty = threadIdx.y;     // 32 x 8
  const float* pb = pts + (size_t)b*DIM*NPTS;
#pragma unroll
  for (int j=0;j<32;j+=8)
    tile[ty+j][tx] = pb[(size_t)(c0+ty+j)*NPTS + n0+tx];
  __syncthreads();
  float* ob = g_ptsT + (size_t)b*NPTS*DIM;
#pragma unroll
  for (int j=0;j<32;j+=8)
    ob[(size_t)(n0+ty+j)*DIM + c0+tx] = tile[tx][ty+j];
}

// ---------------- GEMM (R11 loop, A tile DUPLICATED in smem) ---------------
// sAd[k][2m] = sAd[k][2m+1] = a[m][k]  (stride AD=132 floats).
// Thread's 4 rows tm*4..tm*4+3 -> two LDS.128 give (a0,a0,a1,a1),(a2,a2,a3,a3)
// directly as u64 FFMA2 operands — zero splat MOVs, values bit-identical.
// MODE 0: layer1 — gather A from ptsT/ball/xyz (K=68, wld=67)
// MODE 1: layer2 — A = prev H with fused BN+ReLU (K=64)
// MODE 2: layer3 — as MODE1, no H store, + max/min pool epilogue (BN=128)
#define AD 132
template<int K, int BN, int MODE>
__global__ __launch_bounds__(256) void gemm_kernel(const float* __restrict__ A,
    const float* __restrict__ W, int wld,
    const float* __restrict__ bias, float* __restrict__ H,
    const float* __restrict__ xyz){
  constexpr bool GATHER = (MODE==0);
  constexpr bool AFF    = (MODE>=1);
  constexpr bool POOL   = (MODE==2);
  extern __shared__ float sm[];
  float* sAd   = sm;                    // [K][AD]  duplicated A tile
  float* sB    = sAd + K*AD;            // [K][BN+4]
  float* sbias = sB + K*(BN+4);         // BN
  float* ssc   = sbias + BN;            // K (AFF only)
  float* ssh   = ssc + K;
  __shared__ int   sn[64];
  __shared__ float sctr[6];
  const int tid = threadIdx.x;
  const int m0  = blockIdx.x*64;

  for (int o=tid;o<BN;o+=256) sbias[o]=bias[o];
  if (AFF) for (int cc=tid; cc<K; cc+=256){ ssc[cc]=g_scale[cc]; ssh[cc]=g_shift[cc]; }
  for (int idx=tid; idx<BN*wld; idx+=256){
    int o=idx/wld, cc=idx-o*wld;
    sB[cc*(BN+4)+o]=W[idx];
  }
  if (K>wld) for (int o=tid;o<BN;o+=256) sB[(K-1)*(BN+4)+o]=0.f;

  if (GATHER){
    if (tid<64) sn[tid] = g_ball[(size_t)m0 + tid];
    if (tid>=64 && tid<70) sctr[tid-64] = g_new_xyz[(m0>>5)*3 + (tid-64)];
    __syncthreads();
    const int b = blockIdx.x >> 9;      // 512 blocks per batch
    // m-fast: lanes span m 0..31 -> STS.64 2-phase, conflict-light
    for (int idx=tid; idx<64*16; idx+=256){
      int c4 = idx >> 6;                // 0..15
      int m  = idx & 63;                // 0..63
      int n  = sn[m];
      float4 v = *(const float4*)(g_ptsT + ((size_t)b*NPTS + n)*DIM + c4*4);
      int cc=3+c4*4;
      *(float2*)&sAd[(cc  )*AD+2*m] = make_float2(v.x,v.x);
      *(float2*)&sAd[(cc+1)*AD+2*m] = make_float2(v.y,v.y);
      *(float2*)&sAd[(cc+2)*AD+2*m] = make_float2(v.z,v.z);
      *(float2*)&sAd[(cc+3)*AD+2*m] = make_float2(v.w,v.w);
    }
    if (tid<64){
      int n=sn[tid];
      const float* xb = xyz + (size_t)b*3*NPTS;
      const int grp = (tid>>5)*3;
      float f0 = __fsub_rn(xb[n],        sctr[grp+0]);
      float f1 = __fsub_rn(xb[NPTS+n],   sctr[grp+1]);
      float f2 = __fsub_rn(xb[2*NPTS+n], sctr[grp+2]);
      *(float2*)&sAd[0*AD+2*tid]  = make_float2(f0,f0);
      *(float2*)&sAd[1*AD+2*tid]  = make_float2(f1,f1);
      *(float2*)&sAd[2*AD+2*tid]  = make_float2(f2,f2);
      *(float2*)&sAd[67*AD+2*tid] = make_float2(0.f,0.f);
    }
  } else {
    __syncthreads();                    // ssc/ssh visible
    constexpr int K4 = K/4;
    const float4* A4 = (const float4*)A;
    for (int idx=tid; idx<64*K4; idx+=256){
      int m=idx/K4, c4=idx-m*K4;
      float4 v = A4[(size_t)(m0+m)*K4 + c4];
      int cc=c4*4;
      v.x = fmaxf(fmaf(v.x, ssc[cc  ], ssh[cc  ]), 0.f);
      v.y = fmaxf(fmaf(v.y, ssc[cc+1], ssh[cc+1]), 0.f);
      v.z = fmaxf(fmaf(v.z, ssc[cc+2], ssh[cc+2]), 0.f);
      v.w = fmaxf(fmaf(v.w, ssc[cc+3], ssh[cc+3]), 0.f);
      *(float2*)&sAd[(cc  )*AD+2*m] = make_float2(v.x,v.x);
      *(float2*)&sAd[(cc+1)*AD+2*m] = make_float2(v.y,v.y);
      *(float2*)&sAd[(cc+2)*AD+2*m] = make_float2(v.z,v.z);
      *(float2*)&sAd[(cc+3)*AD+2*m] = make_float2(v.w,v.w);
    }
  }
  __syncthreads();

  // ---- main loop: R11 FFMA2 sequence, A operands straight from LDS.128 ----
  constexpr int NPT = BN/16;            // 4 or 8 output cols per thread
  constexpr int NP2 = NPT/2;
  const int tm = tid>>4, tn = tid&15;
  u64 acc[4][NP2];
#pragma unroll
  for (int i=0;i<4;i++)
#pragma unroll
    for (int j=0;j<NP2;j++) acc[i][j]=pack2(sbias[tn*NPT+2*j],sbias[tn*NPT+2*j+1]);

  const float* Adp = sAd + 8*tm;        // float index of (a0,a0) at row k
  const float* Bp  = sB + tn*NPT;
#pragma unroll 4
  for (int k=0;k<K;k++){
    float4 p0 = *(const float4*)(Adp + k*AD);      // (a0,a0,a1,a1)
    float4 p1 = *(const float4*)(Adp + k*AD + 4);  // (a2,a2,a3,a3)
    u64 a0=((const u64*)&p0)[0], a1=((const u64*)&p0)[1];
    u64 a2=((const u64*)&p1)[0], a3=((const u64*)&p1)[1];
    u64 b2[NP2];
    const float4* b4 = (const float4*)(Bp + k*(BN+4));
#pragma unroll
    for (int j=0;j<NP2/2;j++){
      float4 t=b4[j];
      b2[2*j]=pack2(t.x,t.y); b2[2*j+1]=pack2(t.z,t.w);
    }
#pragma unroll
    for (int j=0;j<NP2;j++){
      fma2(acc[0][j],a0,b2[j]);
      fma2(acc[1][j],a1,b2[j]);
      fma2(acc[2][j],a2,b2[j]);
      fma2(acc[3][j],a3,b2[j]);
    }
  }

  float vals[4][NPT];
#pragma unroll
  for (int i=0;i<4;i++)
#pragma unroll
    for (int j=0;j<NP2;j++) unpack2(vals[i][2*j], vals[i][2*j+1], acc[i][j]);

  if (!POOL){
#pragma unroll
    for (int i=0;i<4;i++){
      float* outp = H + (size_t)(m0+tm*4+i)*BN + tn*NPT;
#pragma unroll
      for (int j=0;j<NPT/4;j++){
        float4 t; t.x=vals[i][4*j]; t.y=vals[i][4*j+1]; t.z=vals[i][4*j+2]; t.w=vals[i][4*j+3];
        *(float4*)(outp + 4*j) = t;
      }
    }
  }

  // ---- deterministic column sum / sumsq (as R11) ----
  __syncthreads();
  float* sS  = sm;                      // [BN][16]
  float* sSS = sm + 16*BN;              // [BN][16]
#pragma unroll
  for (int j=0;j<NPT;j++){
    float v0=vals[0][j], v1=vals[1][j], v2=vals[2][j], v3=vals[3][j];
    sS [(tn*NPT+j)*16 + tm] = ((v0+v1)+v2)+v3;
    sSS[(tn*NPT+j)*16 + tm] = ((v0*v0+v1*v1)+v2*v2)+v3*v3;
  }
  __syncthreads();
  if (tid < BN){
    float s=0.f, ss=0.f;
#pragma unroll
    for (int t=0;t<16;t++){ s+=sS[tid*16+t]; ss+=sSS[tid*16+t]; }
    g_pS [(size_t)tid*NBLK + blockIdx.x] = s;
    g_pSS[(size_t)tid*NBLK + blockIdx.x] = ss;
  }

  if (POOL){
    // rows tm*4..tm*4+3 all lie in sample group tm>>3 (32 rows per sample)
    __syncthreads();
#pragma unroll
    for (int j=0;j<NPT;j++){
      float mx = fmaxf(fmaxf(vals[0][j],vals[1][j]), fmaxf(vals[2][j],vals[3][j]));
      float mn = fminf(fminf(vals[0][j],vals[1][j]), fminf(vals[2][j],vals[3][j]));
      sS [(tn*NPT+j)*16 + tm] = mx;
      sSS[(tn*NPT+j)*16 + tm] = mn;
    }
    __syncthreads();
    // 256 threads -> (grp 0..1) x (col 0..127)
    {
      int grp = tid>>7, col = tid&127;
      float mx=-3.4e38f, mn=3.4e38f;
#pragma unroll
      for (int t=0;t<8;t++){
        mx = fmaxf(mx, sS [col*16 + grp*8 + t]);
        mn = fminf(mn, sSS[col*16 + grp*8 + t]);
      }
      size_t gidx = (size_t)(blockIdx.x*2+grp)*128 + col;
      g_mx[gidx]=mx; g_mn[gidx]=mn;
    }
  }
}

// ---------------- BN stats: one block per channel ---------------------------
__global__ void bnstats_kernel(const float* __restrict__ g, const float* __restrict__ beta){
  __shared__ float sh[512];
  const int c=blockIdx.x, t=threadIdx.x;   // 256 threads
  float s=0.f, ss=0.f;
  const float* ps  = g_pS  + (size_t)c*NBLK;
  const float* pss = g_pSS + (size_t)c*NBLK;
  for (int i=t;i<NBLK;i+=256){ s+=ps[i]; ss+=pss[i]; }
  sh[t]=s; sh[256+t]=ss; __syncthreads();
  for (int o=128;o>0;o>>=1){
    if (t<o){ sh[t]+=sh[t+o]; sh[256+t]+=sh[256+t+o]; }
    __syncthreads();
  }
  if (t==0){
    const float inv = 1.0f/(float)MROWS;
    float mean = sh[0]*inv;
    float var  = sh[256]*inv - mean*mean;
    float rstd = rsqrtf(var + 1e-5f);
    float sc   = rstd*g[c];
    g_scale[c] = sc;
    g_shift[c] = beta[c] - mean*sc;
  }
}

// ---------------- final pool: norm+relu on pre-reduced max/min -------------
__global__ void pool_kernel(float* __restrict__ out){
  const int gq=blockIdx.x;                   // 0..8191 (b*1024+s)
  const int o =threadIdx.x;                  // 0..127
  const int b=gq>>10, s=gq&1023;
  const float sc=g_scale[o], sh=g_shift[o];
  const float mx=g_mx[(size_t)gq*128+o], mn=g_mn[(size_t)gq*128+o];
  float v = (sc>=0.f)? fmaf(mx,sc,sh) : fmaf(mn,sc,sh);
  out[24576 + (size_t)b*131072 + (size_t)o*1024 + s] = fmaxf(v, 0.f);
}

// ---------------- launch ----------------------------------------------------
extern "C" void kernel_launch(void* const* d_in, const int* in_sizes, int n_in,
                              void* d_out, int out_size){
  (void)in_sizes; (void)n_in; (void)out_size;
  const float* xyz = (const float*)d_in[0];
  const float* pts = (const float*)d_in[1];
  const float* w0  = (const float*)d_in[2];
  const float* b0  = (const float*)d_in[3];
  const float* gg0 = (const float*)d_in[4];
  const float* be0 = (const float*)d_in[5];
  const float* w1  = (const float*)d_in[6];
  const float* b1  = (const float*)d_in[7];
  const float* gg1 = (const float*)d_in[8];
  const float* be1 = (const float*)d_in[9];
  const float* w2  = (const float*)d_in[10];
  const float* b2  = (const float*)d_in[11];
  const float* gg2 = (const float*)d_in[12];
  const float* be2 = (const float*)d_in[13];
  float* out = (float*)d_out;

  // smem sizes (floats): K*AD + K*(BN+4) + BN + 2*K (AFF)
  const int smem1 = (68*AD + 68*68 + 64)*4;            // 54656
  const int smem2 = (64*AD + 64*68 + 64  + 2*64)*4;    // 51968+... recompute below
  const int smem2x = (64*AD + 64*68 + 64 + 128)*4;     // 52480
  const int smem3 = (64*AD + 64*132 + 128 + 128)*4;    // 68608
  (void)smem2;

  cudaFuncSetAttribute(fps_kernel, cudaFuncAttributeMaxDynamicSharedMemorySize, 3*NPTS*4);
  cudaFuncSetAttribute((const void*)gemm_kernel<68,64,0>,
                       cudaFuncAttributeMaxDynamicSharedMemorySize, smem1);
  cudaFuncSetAttribute((const void*)gemm_kernel<64,64,1>,
                       cudaFuncAttributeMaxDynamicSharedMemorySize, smem2x);
  cudaFuncSetAttribute((const void*)gemm_kernel<64,128,2>,
                       cudaFuncAttributeMaxDynamicSharedMemorySize, smem3);

  float *pH1,*pH2;
  cudaGetSymbolAddress((void**)&pH1, g_h1);
  cudaGetSymbolAddress((void**)&pH2, g_h2);

  fps_kernel<<<BATCH, 1024, 3*NPTS*4>>>(xyz);
  newxyz_kernel<<<BATCH, SPTS>>>(xyz, out);
  ball_kernel<<<1024, 256>>>(xyz);
  transpose_kernel<<<dim3(NPTS/32, DIM/32, BATCH), dim3(32,8)>>>(pts);

  gemm_kernel<68,64,0><<<NBLK, 256, smem1>>>(nullptr, w0, 67, b0, pH1, xyz);
  bnstats_kernel<<<64, 256>>>(gg0, be0);

  gemm_kernel<64,64,1><<<NBLK, 256, smem2x>>>(pH1, w1, 64, b1, pH2, xyz);
  bnstats_kernel<<<64, 256>>>(gg1, be1);

  gemm_kernel<64,128,2><<<NBLK, 256, smem3>>>(pH2, w2, 64, b2, nullptr, xyz);
  bnstats_kernel<<<128, 256>>>(gg2, be2);

  pool_kernel<<<BATCH*SPTS, 128>>>(out);
}

// round 15
// speedup vs baseline: 1.1087x; 1.1087x over previous
#include <cuda_runtime.h>
#include <cstdint>

#define BATCH   8
#define NPTS    8192
#define DIM     64
#define SPTS    1024      // NPOINT
#define NS      32        // NSAMPLE
#define MROWS   (BATCH*SPTS*NS)   // 262144
#define NBLK    (MROWS/64)        // 4096 gemm blocks

typedef unsigned long long u64;

// ---------------- f32x2 packed helpers --------------------------------------
__device__ __forceinline__ u64 pack2(float lo, float hi){
  u64 r; asm("mov.b64 %0,{%1,%2};" : "=l"(r) : "f"(lo), "f"(hi)); return r;
}
__device__ __forceinline__ void unpack2(float& lo, float& hi, u64 p){
  asm("mov.b64 {%0,%1},%2;" : "=f"(lo), "=f"(hi) : "l"(p));
}
__device__ __forceinline__ u64 add2(u64 a, u64 b){
  u64 r; asm("add.rn.f32x2 %0,%1,%2;" : "=l"(r) : "l"(a), "l"(b)); return r;
}
__device__ __forceinline__ u64 mul2(u64 a, u64 b){
  u64 r; asm("mul.rn.f32x2 %0,%1,%2;" : "=l"(r) : "l"(a), "l"(b)); return r;
}
__device__ __forceinline__ void fma2(u64& d, u64 a, u64 b){
  asm("fma.rn.f32x2 %0,%1,%2,%0;" : "+l"(d) : "l"(a), "l"(b));
}

// ---------------- scratch ---------------------------------------------------
__device__ int   g_fps_idx[BATCH*SPTS];
__device__ float g_new_xyz[BATCH*SPTS*3];
__device__ int   g_ball[BATCH*SPTS*NS];
__device__ float g_ptsT[BATCH*NPTS*DIM];
__device__ float g_h1[(size_t)MROWS*64];
__device__ float g_h2[(size_t)MROWS*64];
__device__ float g_mx[(size_t)BATCH*SPTS*128];
__device__ float g_mn[(size_t)BATCH*SPTS*128];
__device__ float g_pS [(size_t)128*NBLK];   // channel-major
__device__ float g_pSS[(size_t)128*NBLK];
__device__ float g_scale[128];
__device__ float g_shift[128];

// ---------------- FPS: byte-identical to R11 (proven 1043) ------------------
__global__ __launch_bounds__(1024,1) void fps_kernel(const float* __restrict__ xyz){
  extern __shared__ float sxyz[];            // 3*8192 floats
  __shared__ unsigned swarp[32];
  __shared__ unsigned srev[2];
  const int b   = blockIdx.x;
  const int tid = threadIdx.x;
  const float* xb = xyz + (size_t)b*3*NPTS;
  for (int i=tid; i<3*NPTS; i+=1024) sxyz[i]=xb[i];
  if (tid<2) srev[tid]=0u;
  __syncthreads();

  u64 rx2[4], ry2[4], rz2[4];
  float rdl[4], rdh[4];
#pragma unroll
  for (int j=0;j<4;j++){
    int plo=j*1024+tid, phi=(j+4)*1024+tid;
    rx2[j]=pack2(sxyz[plo],       sxyz[phi]);
    ry2[j]=pack2(sxyz[NPTS+plo],  sxyz[NPTS+phi]);
    rz2[j]=pack2(sxyz[2*NPTS+plo],sxyz[2*NPTS+phi]);
    rdl[j]=1e10f; rdh[j]=1e10f;
  }
  int far=0, p=0;
  const int lane=tid&31, wid=tid>>5;
  const unsigned base = (unsigned)(NPTS-1-tid);

  for (int it=0; it<SPTS; ++it){
    if (tid==0) g_fps_idx[b*SPTS+it]=far;
    const float cx=sxyz[far], cy=sxyz[NPTS+far], cz=sxyz[2*NPTS+far];
    const u64 ncx=pack2(-cx,-cx), ncy=pack2(-cy,-cy), ncz=pack2(-cz,-cz);
    float m=0.f;
#pragma unroll
    for (int j=0;j<4;j++){
      u64 dx=add2(rx2[j],ncx);            // x + (-c) == x - c (IEEE)
      u64 dy=add2(ry2[j],ncy);
      u64 dz=add2(rz2[j],ncz);
      u64 s2=add2(add2(mul2(dx,dx),mul2(dy,dy)),mul2(dz,dz));
      float dl,dh; unpack2(dl,dh,s2);
      float nl=fminf(rdl[j],dl), nh=fminf(rdh[j],dh);
      rdl[j]=nl; rdh[j]=nh;
      m = fmaxf(m, fmaxf(nl,nh));
    }
    const unsigned wbits = __reduce_max_sync(0xffffffffu, __float_as_uint(m));
    if (lane==0) swarp[wid]=wbits;
    __syncthreads();                       // (1) warp maxima ready
    const unsigned vbits = __reduce_max_sync(0xffffffffu, swarp[lane]);
    const float vmax = __uint_as_float(vbits);
    if (wbits==vbits){                     // WARP-UNIFORM guard
      unsigned rev=0u;
#pragma unroll
      for (int j=0;j<4;j++){
        if (rdl[j]==vmax){ unsigned r=base-(unsigned)(j<<10);     rev = r>rev?r:rev; }
        if (rdh[j]==vmax){ unsigned r=base-(unsigned)((j+4)<<10); rev = r>rev?r:rev; }
      }
      rev = __reduce_max_sync(0xffffffffu, rev);
      if (lane==0) atomicMax(&srev[p], rev);
    }
    __syncthreads();                       // (2) index ready
    far = (NPTS-1) - (int)srev[p];
    if (tid==0) srev[p^1]=0u;
    p ^= 1;
  }
}

// ---------------- ball query (+ merged new_xyz gather & first output) ------
__global__ void ball_kernel(const float* __restrict__ xyz, float* __restrict__ out){
  const int gw   = (blockIdx.x*blockDim.x + threadIdx.x) >> 5;  // 0..8191
  const int lane = threadIdx.x & 31;
  const int wl   = threadIdx.x >> 5;
  const int b = gw >> 10;
  const int s = gw & 1023;
  __shared__ int sidx[8][NS];
  const float* xb = xyz + (size_t)b*3*NPTS;
  const int ctr = g_fps_idx[gw];
  const float cx = xb[ctr];
  const float cy = xb[NPTS+ctr];
  const float cz = xb[2*NPTS+ctr];
  if (lane<3){
    float v = (lane==0)?cx:((lane==1)?cy:cz);
    g_new_xyz[gw*3+lane]=v;
    out[(size_t)b*3*SPTS + (size_t)lane*SPTS + s]=v;
  }
  unsigned cnt=0;
  for (int basep=0; basep<NPTS; basep+=32){
    int pp = basep+lane;
    float dx=__fsub_rn(cx,xb[pp]);
    float dy=__fsub_rn(cy,xb[NPTS+pp]);
    float dz=__fsub_rn(cz,xb[2*NPTS+pp]);
    float d=__fadd_rn(__fadd_rn(__fmul_rn(dx,dx),__fmul_rn(dy,dy)),__fmul_rn(dz,dz));
    bool in = !(d > 0.04f);
    unsigned mm = __ballot_sync(0xffffffffu, in);
    if (in){
      unsigned r = cnt + __popc(mm & ((1u<<lane)-1u));
      if (r < NS) sidx[wl][r] = pp;
    }
    cnt += __popc(mm);
    if (cnt >= NS) break;
  }
  __syncwarp();
  unsigned c = cnt < NS ? cnt : NS;
  int first = sidx[wl][0];
  int v = (lane < (int)c) ? sidx[wl][lane] : first;
  g_ball[gw*NS + lane] = v;
}

// ---------------- points transpose (B,64,N) -> (B,N,64) --------------------
__global__ void transpose_kernel(const float* __restrict__ pts){
  __shared__ float tile[32][33];
  int b  = blockIdx.z;
  int n0 = blockIdx.x*32;
  int c0 = blockIdx.y*32;
  int tx = threadIdx.x, ty = threadIdx.y;     // 32 x 8
  const float* pb = pts + (size_t)b*DIM*NPTS;
#pragma unroll
  for (int j=0;j<32;j+=8)
    tile[ty+j][tx] = pb[(size_t)(c0+ty+j)*NPTS + n0+tx];
  __syncthreads();
  float* ob = g_ptsT + (size_t)b*NPTS*DIM;
#pragma unroll
  for (int j=0;j<32;j+=8)
    ob[(size_t)(n0+ty+j)*DIM + c0+tx] = tile[tx][ty+j];
}

// ---------------- GEMM (R11-proven core): h = act(A) @ W^T + bias ----------
// MODE 0: layer1 — gather A tile from ptsT/ball/xyz (K=68, wld=67)
// MODE 1: layer2 — A = prev H with fused BN+ReLU (K=64)
// MODE 2: layer3 — as MODE1, no H store, + max/min pool epilogue (BN=128)
template<int K, int BN, int MODE>
__global__ __launch_bounds__(256) void gemm_kernel(const float* __restrict__ A,
    const float* __restrict__ W, int wld,
    const float* __restrict__ bias, float* __restrict__ H,
    const float* __restrict__ xyz){
  constexpr bool GATHER = (MODE==0);
  constexpr bool AFF    = (MODE>=1);
  constexpr bool POOL   = (MODE==2);
  extern __shared__ float sm[];
  float* sAT   = sm;                    // [K][68]  (K-major A tile)
  float* sB    = sAT + K*68;            // [K][BN+4]
  float* sbias = sB + K*(BN+4);         // BN
  float* ssc   = sbias + BN;            // K (AFF only)
  float* ssh   = ssc + K;
  __shared__ int   sn[64];
  __shared__ float sctr[6];
  const int tid = threadIdx.x;
  const int m0  = blockIdx.x*64;

  for (int o=tid;o<BN;o+=256) sbias[o]=bias[o];
  if (AFF) for (int cc=tid; cc<K; cc+=256){ ssc[cc]=g_scale[cc]; ssh[cc]=g_shift[cc]; }
  for (int idx=tid; idx<BN*wld; idx+=256){
    int o=idx/wld, cc=idx-o*wld;
    sB[cc*(BN+4)+o]=W[idx];
  }
  if (K>wld) for (int o=tid;o<BN;o+=256) sB[(K-1)*(BN+4)+o]=0.f;

  if (GATHER){
    if (tid<64) sn[tid] = g_ball[(size_t)m0 + tid];
    if (tid>=64 && tid<70) sctr[tid-64] = g_new_xyz[(m0>>5)*3 + (tid-64)];
    __syncthreads();
    const int b = blockIdx.x >> 9;      // 512 blocks per batch
    // m-fast ordering: warp spans m 0..31 -> conflict-free STS banks
    for (int idx=tid; idx<64*16; idx+=256){
      int c4 = idx >> 6;                // 0..15
      int m  = idx & 63;                // 0..63
      int n  = sn[m];
      float4 v = *(const float4*)(g_ptsT + ((size_t)b*NPTS + n)*DIM + c4*4);
      int cc=3+c4*4;
      sAT[(cc  )*68+m]=v.x;
      sAT[(cc+1)*68+m]=v.y;
      sAT[(cc+2)*68+m]=v.z;
      sAT[(cc+3)*68+m]=v.w;
    }
    if (tid<64){
      int n=sn[tid];
      const float* xb = xyz + (size_t)b*3*NPTS;
      const int grp = (tid>>5)*3;
      sAT[0*68+tid] = __fsub_rn(xb[n],        sctr[grp+0]);
      sAT[1*68+tid] = __fsub_rn(xb[NPTS+n],   sctr[grp+1]);
      sAT[2*68+tid] = __fsub_rn(xb[2*NPTS+n], sctr[grp+2]);
      sAT[67*68+tid]= 0.f;
    }
  } else {
    __syncthreads();                    // ssc/ssh visible
    constexpr int K4 = K/4;
    const float4* A4 = (const float4*)A;
    for (int idx=tid; idx<64*K4; idx+=256){
      int m=idx/K4, c4=idx-m*K4;
      float4 v = A4[(size_t)(m0+m)*K4 + c4];
      int cc=c4*4;
      v.x = fmaxf(fmaf(v.x, ssc[cc  ], ssh[cc  ]), 0.f);
      v.y = fmaxf(fmaf(v.y, ssc[cc+1], ssh[cc+1]), 0.f);
      v.z = fmaxf(fmaf(v.z, ssc[cc+2], ssh[cc+2]), 0.f);
      v.w = fmaxf(fmaf(v.w, ssc[cc+3], ssh[cc+3]), 0.f);
      sAT[(cc  )*68+m]=v.x;
      sAT[(cc+1)*68+m]=v.y;
      sAT[(cc+2)*68+m]=v.z;
      sAT[(cc+3)*68+m]=v.w;
    }
  }
  __syncthreads();

  // ---- main loop: byte-identical to R11 ----
  constexpr int NPT = BN/16;            // 4 or 8 output cols per thread
  constexpr int NP2 = NPT/2;
  const int tm = tid>>4, tn = tid&15;
  u64 acc[4][NP2];
#pragma unroll
  for (int i=0;i<4;i++)
#pragma unroll
    for (int j=0;j<NP2;j++) acc[i][j]=pack2(sbias[tn*NPT+2*j],sbias[tn*NPT+2*j+1]);

  const float* ApT = sAT + tm*4;
  const float* Bp  = sB + tn*NPT;
#pragma unroll 4
  for (int k=0;k<K;k++){
    float4 av = *(const float4*)(ApT + k*68);
    u64 a0=pack2(av.x,av.x), a1=pack2(av.y,av.y),
        a2=pack2(av.z,av.z), a3=pack2(av.w,av.w);
    u64 b2[NP2];
    const float4* b4 = (const float4*)(Bp + k*(BN+4));
#pragma unroll
    for (int j=0;j<NP2/2;j++){
      float4 t=b4[j];
      b2[2*j]=pack2(t.x,t.y); b2[2*j+1]=pack2(t.z,t.w);
    }
#pragma unroll
    for (int j=0;j<NP2;j++){
      fma2(acc[0][j],a0,b2[j]);
      fma2(acc[1][j],a1,b2[j]);
      fma2(acc[2][j],a2,b2[j]);
      fma2(acc[3][j],a3,b2[j]);
    }
  }

  float vals[4][NPT];
#pragma unroll
  for (int i=0;i<4;i++)
#pragma unroll
    for (int j=0;j<NP2;j++) unpack2(vals[i][2*j], vals[i][2*j+1], acc[i][j]);

  if (!POOL){
#pragma unroll
    for (int i=0;i<4;i++){
      float* outp = H + (size_t)(m0+tm*4+i)*BN + tn*NPT;
#pragma unroll
      for (int j=0;j<NPT/4;j++){
        float4 t; t.x=vals[i][4*j]; t.y=vals[i][4*j+1]; t.z=vals[i][4*j+2]; t.w=vals[i][4*j+3];
        *(float4*)(outp + 4*j) = t;
      }
    }
  }

  // ---- deterministic column sum / sumsq (as R11) ----
  __syncthreads();
  float* sS  = sm;                      // [BN][16]
  float* sSS = sm + 16*BN;              // [BN][16]
#pragma unroll
  for (int j=0;j<NPT;j++){
    float v0=vals[0][j], v1=vals[1][j], v2=vals[2][j], v3=vals[3][j];
    sS [(tn*NPT+j)*16 + tm] = ((v0+v1)+v2)+v3;
    sSS[(tn*NPT+j)*16 + tm] = ((v0*v0+v1*v1)+v2*v2)+v3*v3;
  }
  __syncthreads();
  if (tid < BN){
    float s=0.f, ss=0.f;
#pragma unroll
    for (int t=0;t<16;t++){ s+=sS[tid*16+t]; ss+=sSS[tid*16+t]; }
    g_pS [(size_t)tid*NBLK + blockIdx.x] = s;
    g_pSS[(size_t)tid*NBLK + blockIdx.x] = ss;
  }

  if (POOL){
    // rows tm*4..tm*4+3 all lie in sample group tm>>3 (32 rows per sample)
    __syncthreads();
#pragma unroll
    for (int j=0;j<NPT;j++){
      float mx = fmaxf(fmaxf(vals[0][j],vals[1][j]), fmaxf(vals[2][j],vals[3][j]));
      float mn = fminf(fminf(vals[0][j],vals[1][j]), fminf(vals[2][j],vals[3][j]));
      sS [(tn*NPT+j)*16 + tm] = mx;
      sSS[(tn*NPT+j)*16 + tm] = mn;
    }
    __syncthreads();
    // 256 threads -> (grp 0..1) x (col 0..127)
    {
      int grp = tid>>7, col = tid&127;
      float mx=-3.4e38f, mn=3.4e38f;
#pragma unroll
      for (int t=0;t<8;t++){
        mx = fmaxf(mx, sS [col*16 + grp*8 + t]);
        mn = fminf(mn, sSS[col*16 + grp*8 + t]);
      }
      size_t gidx = (size_t)(blockIdx.x*2+grp)*128 + col;
      g_mx[gidx]=mx; g_mn[gidx]=mn;
    }
  }
}

// ---------------- BN stats (+ optional fused final pool output) -------------
template<bool POOLOUT>
__global__ void bnstats_kernel(const float* __restrict__ g, const float* __restrict__ beta,
                               float* __restrict__ out){
  __shared__ float sh[512];
  __shared__ float sscsh[2];
  const int c=blockIdx.x, t=threadIdx.x;   // 256 threads
  float s=0.f, ss=0.f;
  const float* ps  = g_pS  + (size_t)c*NBLK;
  const float* pss = g_pSS + (size_t)c*NBLK;
  for (int i=t;i<NBLK;i+=256){ s+=ps[i]; ss+=pss[i]; }
  sh[t]=s; sh[256+t]=ss; __syncthreads();
  for (int o=128;o>0;o>>=1){
    if (t<o){ sh[t]+=sh[t+o]; sh[256+t]+=sh[256+t+o]; }
    __syncthreads();
  }
  if (t==0){
    const float inv = 1.0f/(float)MROWS;
    float mean = sh[0]*inv;
    float var  = sh[256]*inv - mean*mean;
    float rstd = rsqrtf(var + 1e-5f);
    float sc   = rstd*g[c];
    float shv  = beta[c] - mean*sc;
    g_scale[c] = sc;
    g_shift[c] = shv;
    sscsh[0]=sc; sscsh[1]=shv;
  }
  if (POOLOUT){
    __syncthreads();
    const float sc = sscsh[0], shv = sscsh[1];
    const bool pos = (sc>=0.f);
    for (int gq=t; gq<BATCH*SPTS; gq+=256){
      float mv = pos ? g_mx[(size_t)gq*128+c] : g_mn[(size_t)gq*128+c];
      float v  = fmaf(mv, sc, shv);
      int b = gq>>10, sq = gq&1023;
      out[24576 + (size_t)b*131072 + (size_t)c*1024 + sq] = fmaxf(v, 0.f);
    }
  }
}

// ---------------- launch ----------------------------------------------------
extern "C" void kernel_launch(void* const* d_in, const int* in_sizes, int n_in,
                              void* d_out, int out_size){
  (void)in_sizes; (void)n_in; (void)out_size;
  const float* xyz = (const float*)d_in[0];
  const float* pts = (const float*)d_in[1];
  const float* w0  = (const float*)d_in[2];
  const float* b0  = (const float*)d_in[3];
  const float* gg0 = (const float*)d_in[4];
  const float* be0 = (const float*)d_in[5];
  const float* w1  = (const float*)d_in[6];
  const float* b1  = (const float*)d_in[7];
  const float* gg1 = (const float*)d_in[8];
  const float* be1 = (const float*)d_in[9];
  const float* w2  = (const float*)d_in[10];
  const float* b2  = (const float*)d_in[11];
  const float* gg2 = (const float*)d_in[12];
  const float* be2 = (const float*)d_in[13];
  float* out = (float*)d_out;

  // smem sizes (floats): K*68 + K*(BN+4) + BN + 2*K (AFF)
  const int smem1 = (68*68 + 68*68 + 64)*4;           // 37248
  const int smem2 = (64*68 + 64*68 + 64  + 2*64)*4;   // 35584
  const int smem3 = (64*68 + 64*132+ 128 + 2*64)*4;   // 52224

  cudaFuncSetAttribute(fps_kernel, cudaFuncAttributeMaxDynamicSharedMemorySize, 3*NPTS*4);
  cudaFuncSetAttribute((const void*)gemm_kernel<68,64,0>,
                       cudaFuncAttributeMaxDynamicSharedMemorySize, smem1);
  cudaFuncSetAttribute((const void*)gemm_kernel<64,64,1>,
                       cudaFuncAttributeMaxDynamicSharedMemorySize, smem2);
  cudaFuncSetAttribute((const void*)gemm_kernel<64,128,2>,
                       cudaFuncAttributeMaxDynamicSharedMemorySize, smem3);

  float *pH1,*pH2;
  cudaGetSymbolAddress((void**)&pH1, g_h1);
  cudaGetSymbolAddress((void**)&pH2, g_h2);

  fps_kernel<<<BATCH, 1024, 3*NPTS*4>>>(xyz);
  ball_kernel<<<1024, 256>>>(xyz, out);
  transpose_kernel<<<dim3(NPTS/32, DIM/32, BATCH), dim3(32,8)>>>(pts);

  gemm_kernel<68,64,0><<<NBLK, 256, smem1>>>(nullptr, w0, 67, b0, pH1, xyz);
  bnstats_kernel<false><<<64, 256>>>(gg0, be0, nullptr);

  gemm_kernel<64,64,1><<<NBLK, 256, smem2>>>(pH1, w1, 64, b1, pH2, xyz);
  bnstats_kernel<false><<<64, 256>>>(gg1, be1, nullptr);

  gemm_kernel<64,128,2><<<NBLK, 256, smem3>>>(pH2, w2, 64, b2, nullptr, xyz);
  bnstats_kernel<true><<<128, 256>>>(gg2, be2, out);
}

// round 16
// speedup vs baseline: 1.2786x; 1.1532x over previous
#include <cuda_runtime.h>
#include <cstdint>

#define BATCH   8
#define NPTS    8192
#define DIM     64
#define SPTS    1024      // NPOINT
#define NS      32        // NSAMPLE
#define MROWS   (BATCH*SPTS*NS)   // 262144
#define NBLK    (MROWS/128)       // 2048 gemm blocks (128-row tiles)
#define AST     132               // A-tile row stride (128 + 4 pad)

typedef unsigned long long u64;

// ---------------- f32x2 packed helpers --------------------------------------
__device__ __forceinline__ u64 pack2(float lo, float hi){
  u64 r; asm("mov.b64 %0,{%1,%2};" : "=l"(r) : "f"(lo), "f"(hi)); return r;
}
__device__ __forceinline__ void unpack2(float& lo, float& hi, u64 p){
  asm("mov.b64 {%0,%1},%2;" : "=f"(lo), "=f"(hi) : "l"(p));
}
__device__ __forceinline__ u64 add2(u64 a, u64 b){
  u64 r; asm("add.rn.f32x2 %0,%1,%2;" : "=l"(r) : "l"(a), "l"(b)); return r;
}
__device__ __forceinline__ u64 mul2(u64 a, u64 b){
  u64 r; asm("mul.rn.f32x2 %0,%1,%2;" : "=l"(r) : "l"(a), "l"(b)); return r;
}
__device__ __forceinline__ void fma2(u64& d, u64 a, u64 b){
  asm("fma.rn.f32x2 %0,%1,%2,%0;" : "+l"(d) : "l"(a), "l"(b));
}

// ---------------- scratch ---------------------------------------------------
__device__ int   g_fps_idx[BATCH*SPTS];
__device__ float g_new_xyz[BATCH*SPTS*3];
__device__ int   g_ball[BATCH*SPTS*NS];
__device__ float g_ptsT[BATCH*NPTS*DIM];
__device__ float g_h1[(size_t)MROWS*64];
__device__ float g_h2[(size_t)MROWS*64];
__device__ float g_mx[(size_t)BATCH*SPTS*128];
__device__ float g_mn[(size_t)BATCH*SPTS*128];
__device__ float g_pS [(size_t)128*NBLK];   // channel-major
__device__ float g_pSS[(size_t)128*NBLK];
__device__ float g_scale[128];
__device__ float g_shift[128];

// ---------------- FPS: byte-identical to R11/R15 ----------------------------
__global__ __launch_bounds__(1024,1) void fps_kernel(const float* __restrict__ xyz){
  extern __shared__ float sxyz[];            // 3*8192 floats
  __shared__ unsigned swarp[32];
  __shared__ unsigned srev[2];
  const int b   = blockIdx.x;
  const int tid = threadIdx.x;
  const float* xb = xyz + (size_t)b*3*NPTS;
  for (int i=tid; i<3*NPTS; i+=1024) sxyz[i]=xb[i];
  if (tid<2) srev[tid]=0u;
  __syncthreads();

  u64 rx2[4], ry2[4], rz2[4];
  float rdl[4], rdh[4];
#pragma unroll
  for (int j=0;j<4;j++){
    int plo=j*1024+tid, phi=(j+4)*1024+tid;
    rx2[j]=pack2(sxyz[plo],       sxyz[phi]);
    ry2[j]=pack2(sxyz[NPTS+plo],  sxyz[NPTS+phi]);
    rz2[j]=pack2(sxyz[2*NPTS+plo],sxyz[2*NPTS+phi]);
    rdl[j]=1e10f; rdh[j]=1e10f;
  }
  int far=0, p=0;
  const int lane=tid&31, wid=tid>>5;
  const unsigned base = (unsigned)(NPTS-1-tid);

  for (int it=0; it<SPTS; ++it){
    if (tid==0) g_fps_idx[b*SPTS+it]=far;
    const float cx=sxyz[far], cy=sxyz[NPTS+far], cz=sxyz[2*NPTS+far];
    const u64 ncx=pack2(-cx,-cx), ncy=pack2(-cy,-cy), ncz=pack2(-cz,-cz);
    float m=0.f;
#pragma unroll
    for (int j=0;j<4;j++){
      u64 dx=add2(rx2[j],ncx);            // x + (-c) == x - c (IEEE)
      u64 dy=add2(ry2[j],ncy);
      u64 dz=add2(rz2[j],ncz);
      u64 s2=add2(add2(mul2(dx,dx),mul2(dy,dy)),mul2(dz,dz));
      float dl,dh; unpack2(dl,dh,s2);
      float nl=fminf(rdl[j],dl), nh=fminf(rdh[j],dh);
      rdl[j]=nl; rdh[j]=nh;
      m = fmaxf(m, fmaxf(nl,nh));
    }
    const unsigned wbits = __reduce_max_sync(0xffffffffu, __float_as_uint(m));
    if (lane==0) swarp[wid]=wbits;
    __syncthreads();                       // (1) warp maxima ready
    const unsigned vbits = __reduce_max_sync(0xffffffffu, swarp[lane]);
    const float vmax = __uint_as_float(vbits);
    if (wbits==vbits){                     // WARP-UNIFORM guard
      unsigned rev=0u;
#pragma unroll
      for (int j=0;j<4;j++){
        if (rdl[j]==vmax){ unsigned r=base-(unsigned)(j<<10);     rev = r>rev?r:rev; }
        if (rdh[j]==vmax){ unsigned r=base-(unsigned)((j+4)<<10); rev = r>rev?r:rev; }
      }
      rev = __reduce_max_sync(0xffffffffu, rev);
      if (lane==0) atomicMax(&srev[p], rev);
    }
    __syncthreads();                       // (2) index ready
    far = (NPTS-1) - (int)srev[p];
    if (tid==0) srev[p^1]=0u;
    p ^= 1;
  }
}

// ---------------- ball query (+ merged new_xyz gather & first output) ------
__global__ void ball_kernel(const float* __restrict__ xyz, float* __restrict__ out){
  const int gw   = (blockIdx.x*blockDim.x + threadIdx.x) >> 5;  // 0..8191
  const int lane = threadIdx.x & 31;
  const int wl   = threadIdx.x >> 5;
  const int b = gw >> 10;
  const int s = gw & 1023;
  __shared__ int sidx[8][NS];
  const float* xb = xyz + (size_t)b*3*NPTS;
  const int ctr = g_fps_idx[gw];
  const float cx = xb[ctr];
  const float cy = xb[NPTS+ctr];
  const float cz = xb[2*NPTS+ctr];
  if (lane<3){
    float v = (lane==0)?cx:((lane==1)?cy:cz);
    g_new_xyz[gw*3+lane]=v;
    out[(size_t)b*3*SPTS + (size_t)lane*SPTS + s]=v;
  }
  unsigned cnt=0;
  for (int basep=0; basep<NPTS; basep+=32){
    int pp = basep+lane;
    float dx=__fsub_rn(cx,xb[pp]);
    float dy=__fsub_rn(cy,xb[NPTS+pp]);
    float dz=__fsub_rn(cz,xb[2*NPTS+pp]);
    float d=__fadd_rn(__fadd_rn(__fmul_rn(dx,dx),__fmul_rn(dy,dy)),__fmul_rn(dz,dz));
    bool in = !(d > 0.04f);
    unsigned mm = __ballot_sync(0xffffffffu, in);
    if (in){
      unsigned r = cnt + __popc(mm & ((1u<<lane)-1u));
      if (r < NS) sidx[wl][r] = pp;
    }
    cnt += __popc(mm);
    if (cnt >= NS) break;
  }
  __syncwarp();
  unsigned c = cnt < NS ? cnt : NS;
  int first = sidx[wl][0];
  int v = (lane < (int)c) ? sidx[wl][lane] : first;
  g_ball[gw*NS + lane] = v;
}

// ---------------- points transpose (B,64,N) -> (B,N,64) --------------------
__global__ void transpose_kernel(const float* __restrict__ pts){
  __shared__ float tile[32][33];
  int b  = blockIdx.z;
  int n0 = blockIdx.x*32;
  int c0 = blockIdx.y*32;
  int tx = threadIdx.x, ty = threadIdx.y;     // 32 x 8
  const float* pb = pts + (size_t)b*DIM*NPTS;
#pragma unroll
  for (int j=0;j<32;j+=8)
    tile[ty+j][tx] = pb[(size_t)(c0+ty+j)*NPTS + n0+tx];
  __syncthreads();
  float* ob = g_ptsT + (size_t)b*NPTS*DIM;
#pragma unroll
  for (int j=0;j<32;j+=8)
    ob[(size_t)(n0+ty+j)*DIM + c0+tx] = tile[tx][ty+j];
}

// ---------------- GEMM: R11 loop pattern, 128-row M-tile, 8-row threads ----
// Thread tm (0..15) owns rows tm*8..tm*8+7 (contiguous -> A = 2x LDS.128).
// MODE 0: layer1 — gather A from ptsT/ball/xyz (K=68, wld=67)
// MODE 1: layer2 — A = prev H with fused BN+ReLU (K=64)
// MODE 2: layer3 — no H store, + max/min pool epilogue (BN=128, 8x8 tile)
template<int K, int BN, int MODE, int UNR>
__global__ __launch_bounds__(256) void gemm_kernel(const float* __restrict__ A,
    const float* __restrict__ W, int wld,
    const float* __restrict__ bias, float* __restrict__ H,
    const float* __restrict__ xyz){
  constexpr bool GATHER = (MODE==0);
  constexpr bool AFF    = (MODE>=1);
  constexpr bool POOL   = (MODE==2);
  extern __shared__ float sm[];
  float* sAT   = sm;                    // [K][AST]  K-major A tile (128 rows)
  float* sB    = sAT + K*AST;           // [K][BN+4]
  float* sbias = sB + K*(BN+4);         // BN
  float* ssc   = sbias + BN;            // K (AFF only)
  float* ssh   = ssc + K;
  __shared__ int   sn[128];
  __shared__ float sctr[12];
  const int tid = threadIdx.x;
  const int m0  = blockIdx.x*128;

  for (int o=tid;o<BN;o+=256) sbias[o]=bias[o];
  if (AFF) for (int cc=tid; cc<K; cc+=256){ ssc[cc]=g_scale[cc]; ssh[cc]=g_shift[cc]; }
  for (int idx=tid; idx<BN*wld; idx+=256){
    int o=idx/wld, cc=idx-o*wld;
    sB[cc*(BN+4)+o]=W[idx];
  }
  if (K>wld) for (int o=tid;o<BN;o+=256) sB[(K-1)*(BN+4)+o]=0.f;

  if (GATHER){
    if (tid<128) sn[tid] = g_ball[(size_t)m0 + tid];
    if (tid>=128 && tid<140) sctr[tid-128] = g_new_xyz[(m0>>5)*3 + (tid-128)];
    __syncthreads();
    const int b = blockIdx.x >> 8;      // 256 blocks per batch
    // m-fast ordering: warp spans m 0..31 -> conflict-free STS banks
    for (int idx=tid; idx<128*16; idx+=256){
      int c4 = idx >> 7;                // 0..15
      int m  = idx & 127;               // 0..127
      int n  = sn[m];
      float4 v = *(const float4*)(g_ptsT + ((size_t)b*NPTS + n)*DIM + c4*4);
      int cc=3+c4*4;
      sAT[(cc  )*AST+m]=v.x;
      sAT[(cc+1)*AST+m]=v.y;
      sAT[(cc+2)*AST+m]=v.z;
      sAT[(cc+3)*AST+m]=v.w;
    }
    if (tid<128){
      int n=sn[tid];
      const float* xb = xyz + (size_t)b*3*NPTS;
      const int grp = (tid>>5)*3;
      sAT[0*AST+tid] = __fsub_rn(xb[n],        sctr[grp+0]);
      sAT[1*AST+tid] = __fsub_rn(xb[NPTS+n],   sctr[grp+1]);
      sAT[2*AST+tid] = __fsub_rn(xb[2*NPTS+n], sctr[grp+2]);
      sAT[67*AST+tid]= 0.f;
    }
  } else {
    __syncthreads();                    // ssc/ssh visible
    constexpr int K4 = K/4;
    const float4* A4 = (const float4*)A;
    for (int idx=tid; idx<128*K4; idx+=256){
      int m=idx>>4, c4=idx&15;          // K4==16 for MODE>=1
      float4 v = A4[(size_t)(m0+m)*K4 + c4];
      int cc=c4*4;
      v.x = fmaxf(fmaf(v.x, ssc[cc  ], ssh[cc  ]), 0.f);
      v.y = fmaxf(fmaf(v.y, ssc[cc+1], ssh[cc+1]), 0.f);
      v.z = fmaxf(fmaf(v.z, ssc[cc+2], ssh[cc+2]), 0.f);
      v.w = fmaxf(fmaf(v.w, ssc[cc+3], ssh[cc+3]), 0.f);
      sAT[(cc  )*AST+m]=v.x;
      sAT[(cc+1)*AST+m]=v.y;
      sAT[(cc+2)*AST+m]=v.z;
      sAT[(cc+3)*AST+m]=v.w;
    }
  }
  __syncthreads();

  // ---- main loop: 8 rows x NPT cols per thread ----
  constexpr int NPT = BN/16;            // 4 or 8 cols per thread
  constexpr int NP2 = NPT/2;
  const int tm = tid>>4, tn = tid&15;
  u64 acc[8][NP2];
#pragma unroll
  for (int i=0;i<8;i++)
#pragma unroll
    for (int j=0;j<NP2;j++) acc[i][j]=pack2(sbias[tn*NPT+2*j],sbias[tn*NPT+2*j+1]);

  const float* ApT = sAT + tm*8;
  const float* Bp  = sB + tn*NPT;
#pragma unroll UNR
  for (int k=0;k<K;k++){
    float4 av0 = *(const float4*)(ApT + k*AST);      // rows 0..3
    float4 av1 = *(const float4*)(ApT + k*AST + 4);  // rows 4..7
    u64 a[8];
    a[0]=pack2(av0.x,av0.x); a[1]=pack2(av0.y,av0.y);
    a[2]=pack2(av0.z,av0.z); a[3]=pack2(av0.w,av0.w);
    a[4]=pack2(av1.x,av1.x); a[5]=pack2(av1.y,av1.y);
    a[6]=pack2(av1.z,av1.z); a[7]=pack2(av1.w,av1.w);
    u64 b2[NP2];
    const float4* b4 = (const float4*)(Bp + k*(BN+4));
#pragma unroll
    for (int j=0;j<NP2/2;j++){
      float4 t=b4[j];
      b2[2*j]=pack2(t.x,t.y); b2[2*j+1]=pack2(t.z,t.w);
    }
#pragma unroll
    for (int i=0;i<8;i++)
#pragma unroll
      for (int j=0;j<NP2;j++)
        fma2(acc[i][j],a[i],b2[j]);
  }

  float vals[8][NPT];
#pragma unroll
  for (int i=0;i<8;i++)
#pragma unroll
    for (int j=0;j<NP2;j++) unpack2(vals[i][2*j], vals[i][2*j+1], acc[i][j]);

  if (!POOL){
#pragma unroll
    for (int i=0;i<8;i++){
      float* outp = H + (size_t)(m0+tm*8+i)*BN + tn*NPT;
#pragma unroll
      for (int j=0;j<NPT/4;j++){
        float4 t; t.x=vals[i][4*j]; t.y=vals[i][4*j+1]; t.z=vals[i][4*j+2]; t.w=vals[i][4*j+3];
        *(float4*)(outp + 4*j) = t;
      }
    }
  }

  // ---- deterministic column sum / sumsq ----
  __syncthreads();
  float* sS  = sm;                      // [BN][16]
  float* sSS = sm + 16*BN;              // [BN][16]
#pragma unroll
  for (int j=0;j<NPT;j++){
    float s=0.f, ss=0.f;
#pragma unroll
    for (int i=0;i<8;i++){ float v=vals[i][j]; s+=v; ss+=v*v; }
    sS [(tn*NPT+j)*16 + tm] = s;
    sSS[(tn*NPT+j)*16 + tm] = ss;
  }
  __syncthreads();
  if (tid < BN){
    float s=0.f, ss=0.f;
#pragma unroll
    for (int t=0;t<16;t++){ s+=sS[tid*16+t]; ss+=sSS[tid*16+t]; }
    g_pS [(size_t)tid*NBLK + blockIdx.x] = s;
    g_pSS[(size_t)tid*NBLK + blockIdx.x] = ss;
  }

  if (POOL){
    // rows tm*8..tm*8+7 all lie in sample group tm>>2 (32 rows per sample)
    __syncthreads();
#pragma unroll
    for (int j=0;j<NPT;j++){
      float mx=-3.4e38f, mn=3.4e38f;
#pragma unroll
      for (int i=0;i<8;i++){ mx=fmaxf(mx,vals[i][j]); mn=fminf(mn,vals[i][j]); }
      sS [(tn*NPT+j)*16 + tm] = mx;
      sSS[(tn*NPT+j)*16 + tm] = mn;
    }
    __syncthreads();
    // 4 sample groups x 128 cols = 512 outputs with 256 threads
    for (int it=tid; it<4*128; it+=256){
      int grp = it>>7, col = it&127;
      float mx=-3.4e38f, mn=3.4e38f;
#pragma unroll
      for (int t=0;t<4;t++){
        mx = fmaxf(mx, sS [col*16 + grp*4 + t]);
        mn = fminf(mn, sSS[col*16 + grp*4 + t]);
      }
      size_t gidx = (size_t)(blockIdx.x*4+grp)*128 + col;
      g_mx[gidx]=mx; g_mn[gidx]=mn;
    }
  }
}

// ---------------- BN stats (+ optional fused final pool output) -------------
template<bool POOLOUT>
__global__ void bnstats_kernel(const float* __restrict__ g, const float* __restrict__ beta,
                               float* __restrict__ out){
  __shared__ float sh[512];
  __shared__ float sscsh[2];
  const int c=blockIdx.x, t=threadIdx.x;   // 256 threads
  float s=0.f, ss=0.f;
  const float* ps  = g_pS  + (size_t)c*NBLK;
  const float* pss = g_pSS + (size_t)c*NBLK;
  for (int i=t;i<NBLK;i+=256){ s+=ps[i]; ss+=pss[i]; }
  sh[t]=s; sh[256+t]=ss; __syncthreads();
  for (int o=128;o>0;o>>=1){
    if (t<o){ sh[t]+=sh[t+o]; sh[256+t]+=sh[256+t+o]; }
    __syncthreads();
  }
  if (t==0){
    const float inv = 1.0f/(float)MROWS;
    float mean = sh[0]*inv;
    float var  = sh[256]*inv - mean*mean;
    float rstd = rsqrtf(var + 1e-5f);
    float sc   = rstd*g[c];
    float shv  = beta[c] - mean*sc;
    g_scale[c] = sc;
    g_shift[c] = shv;
    sscsh[0]=sc; sscsh[1]=shv;
  }
  if (POOLOUT){
    __syncthreads();
    const float sc = sscsh[0], shv = sscsh[1];
    const bool pos = (sc>=0.f);
    for (int gq=t; gq<BATCH*SPTS; gq+=256){
      float mv = pos ? g_mx[(size_t)gq*128+c] : g_mn[(size_t)gq*128+c];
      float v  = fmaf(mv, sc, shv);
      int b = gq>>10, sq = gq&1023;
      out[24576 + (size_t)b*131072 + (size_t)c*1024 + sq] = fmaxf(v, 0.f);
    }
  }
}

// ---------------- launch ----------------------------------------------------
extern "C" void kernel_launch(void* const* d_in, const int* in_sizes, int n_in,
                              void* d_out, int out_size){
  (void)in_sizes; (void)n_in; (void)out_size;
  const float* xyz = (const float*)d_in[0];
  const float* pts = (const float*)d_in[1];
  const float* w0  = (const float*)d_in[2];
  const float* b0  = (const float*)d_in[3];
  const float* gg0 = (const float*)d_in[4];
  const float* be0 = (const float*)d_in[5];
  const float* w1  = (const float*)d_in[6];
  const float* b1  = (const float*)d_in[7];
  const float* gg1 = (const float*)d_in[8];
  const float* be1 = (const float*)d_in[9];
  const float* w2  = (const float*)d_in[10];
  const float* b2  = (const float*)d_in[11];
  const float* gg2 = (const float*)d_in[12];
  const float* be2 = (const float*)d_in[13];
  float* out = (float*)d_out;

  // smem (floats): K*AST + K*(BN+4) + BN + 2*K (AFF)
  const int smem1 = (68*AST + 68*68 + 64)*4;            // 54656
  const int smem2 = (64*AST + 64*68 + 64 + 128)*4;      // 52480
  const int smem3 = (64*AST + 64*132 + 128 + 128)*4;    // 68608

  cudaFuncSetAttribute(fps_kernel, cudaFuncAttributeMaxDynamicSharedMemorySize, 3*NPTS*4);
  cudaFuncSetAttribute((const void*)gemm_kernel<68,64,0,4>,
                       cudaFuncAttributeMaxDynamicSharedMemorySize, smem1);
  cudaFuncSetAttribute((const void*)gemm_kernel<64,64,1,4>,
                       cudaFuncAttributeMaxDynamicSharedMemorySize, smem2);
  cudaFuncSetAttribute((const void*)gemm_kernel<64,128,2,2>,
                       cudaFuncAttributeMaxDynamicSharedMemorySize, smem3);

  float *pH1,*pH2;
  cudaGetSymbolAddress((void**)&pH1, g_h1);
  cudaGetSymbolAddress((void**)&pH2, g_h2);

  fps_kernel<<<BATCH, 1024, 3*NPTS*4>>>(xyz);
  ball_kernel<<<1024, 256>>>(xyz, out);
  transpose_kernel<<<dim3(NPTS/32, DIM/32, BATCH), dim3(32,8)>>>(pts);

  gemm_kernel<68,64,0,4><<<NBLK, 256, smem1>>>(nullptr, w0, 67, b0, pH1, xyz);
  bnstats_kernel<false><<<64, 256>>>(gg0, be0, nullptr);

  gemm_kernel<64,64,1,4><<<NBLK, 256, smem2>>>(pH1, w1, 64, b1, pH2, xyz);
  bnstats_kernel<false><<<64, 256>>>(gg1, be1, nullptr);

  gemm_kernel<64,128,2,2><<<NBLK, 256, smem3>>>(pH2, w2, 64, b2, nullptr, xyz);
  bnstats_kernel<true><<<128, 256>>>(gg2, be2, out);
}

// round 17
// speedup vs baseline: 1.2877x; 1.0071x over previous
#include <cuda_runtime.h>
#include <cstdint>

#define BATCH   8
#define NPTS    8192
#define DIM     64
#define SPTS    1024      // NPOINT
#define NS      32        // NSAMPLE
#define MROWS   (BATCH*SPTS*NS)   // 262144
#define NBLK    (MROWS/128)       // 2048 gemm blocks (128-row tiles)
#define AST     132               // A-tile row stride (128 + 4 pad)

typedef unsigned long long u64;

// ---------------- f32x2 packed helpers --------------------------------------
__device__ __forceinline__ u64 pack2(float lo, float hi){
  u64 r; asm("mov.b64 %0,{%1,%2};" : "=l"(r) : "f"(lo), "f"(hi)); return r;
}
__device__ __forceinline__ void unpack2(float& lo, float& hi, u64 p){
  asm("mov.b64 {%0,%1},%2;" : "=f"(lo), "=f"(hi) : "l"(p));
}
__device__ __forceinline__ u64 add2(u64 a, u64 b){
  u64 r; asm("add.rn.f32x2 %0,%1,%2;" : "=l"(r) : "l"(a), "l"(b)); return r;
}
__device__ __forceinline__ u64 mul2(u64 a, u64 b){
  u64 r; asm("mul.rn.f32x2 %0,%1,%2;" : "=l"(r) : "l"(a), "l"(b)); return r;
}
__device__ __forceinline__ void fma2(u64& d, u64 a, u64 b){
  asm("fma.rn.f32x2 %0,%1,%2,%0;" : "+l"(d) : "l"(a), "l"(b));
}

// ---------------- scratch ---------------------------------------------------
__device__ int   g_fps_idx[BATCH*SPTS];
__device__ float g_new_xyz[BATCH*SPTS*3];
__device__ int   g_ball[BATCH*SPTS*NS];
__device__ float g_ptsT[BATCH*NPTS*DIM];
__device__ float g_h1[(size_t)MROWS*64];
__device__ float g_h2[(size_t)MROWS*64];
__device__ float g_mx[(size_t)BATCH*SPTS*128];
__device__ float g_mn[(size_t)BATCH*SPTS*128];
__device__ float g_pS [(size_t)128*NBLK];   // channel-major
__device__ float g_pSS[(size_t)128*NBLK];
__device__ float g_scale[128];
__device__ float g_shift[128];

// ---------------- FPS: byte-identical to R11/R15/R16 ------------------------
__global__ __launch_bounds__(1024,1) void fps_kernel(const float* __restrict__ xyz){
  extern __shared__ float sxyz[];            // 3*8192 floats
  __shared__ unsigned swarp[32];
  __shared__ unsigned srev[2];
  const int b   = blockIdx.x;
  const int tid = threadIdx.x;
  const float* xb = xyz + (size_t)b*3*NPTS;
  for (int i=tid; i<3*NPTS; i+=1024) sxyz[i]=xb[i];
  if (tid<2) srev[tid]=0u;
  __syncthreads();

  u64 rx2[4], ry2[4], rz2[4];
  float rdl[4], rdh[4];
#pragma unroll
  for (int j=0;j<4;j++){
    int plo=j*1024+tid, phi=(j+4)*1024+tid;
    rx2[j]=pack2(sxyz[plo],       sxyz[phi]);
    ry2[j]=pack2(sxyz[NPTS+plo],  sxyz[NPTS+phi]);
    rz2[j]=pack2(sxyz[2*NPTS+plo],sxyz[2*NPTS+phi]);
    rdl[j]=1e10f; rdh[j]=1e10f;
  }
  int far=0, p=0;
  const int lane=tid&31, wid=tid>>5;
  const unsigned base = (unsigned)(NPTS-1-tid);

  for (int it=0; it<SPTS; ++it){
    if (tid==0) g_fps_idx[b*SPTS+it]=far;
    const float cx=sxyz[far], cy=sxyz[NPTS+far], cz=sxyz[2*NPTS+far];
    const u64 ncx=pack2(-cx,-cx), ncy=pack2(-cy,-cy), ncz=pack2(-cz,-cz);
    float m=0.f;
#pragma unroll
    for (int j=0;j<4;j++){
      u64 dx=add2(rx2[j],ncx);            // x + (-c) == x - c (IEEE)
      u64 dy=add2(ry2[j],ncy);
      u64 dz=add2(rz2[j],ncz);
      u64 s2=add2(add2(mul2(dx,dx),mul2(dy,dy)),mul2(dz,dz));
      float dl,dh; unpack2(dl,dh,s2);
      float nl=fminf(rdl[j],dl), nh=fminf(rdh[j],dh);
      rdl[j]=nl; rdh[j]=nh;
      m = fmaxf(m, fmaxf(nl,nh));
    }
    const unsigned wbits = __reduce_max_sync(0xffffffffu, __float_as_uint(m));
    if (lane==0) swarp[wid]=wbits;
    __syncthreads();                       // (1) warp maxima ready
    const unsigned vbits = __reduce_max_sync(0xffffffffu, swarp[lane]);
    const float vmax = __uint_as_float(vbits);
    if (wbits==vbits){                     // WARP-UNIFORM guard
      unsigned rev=0u;
#pragma unroll
      for (int j=0;j<4;j++){
        if (rdl[j]==vmax){ unsigned r=base-(unsigned)(j<<10);     rev = r>rev?r:rev; }
        if (rdh[j]==vmax){ unsigned r=base-(unsigned)((j+4)<<10); rev = r>rev?r:rev; }
      }
      rev = __reduce_max_sync(0xffffffffu, rev);
      if (lane==0) atomicMax(&srev[p], rev);
    }
    __syncthreads();                       // (2) index ready
    far = (NPTS-1) - (int)srev[p];
    if (tid==0) srev[p^1]=0u;
    p ^= 1;
  }
}

// ---------------- ball query (+ merged new_xyz gather & first output) ------
__global__ void ball_kernel(const float* __restrict__ xyz, float* __restrict__ out){
  const int gw   = (blockIdx.x*blockDim.x + threadIdx.x) >> 5;  // 0..8191
  const int lane = threadIdx.x & 31;
  const int wl   = threadIdx.x >> 5;
  const int b = gw >> 10;
  const int s = gw & 1023;
  __shared__ int sidx[8][NS];
  const float* xb = xyz + (size_t)b*3*NPTS;
  const int ctr = g_fps_idx[gw];
  const float cx = xb[ctr];
  const float cy = xb[NPTS+ctr];
  const float cz = xb[2*NPTS+ctr];
  if (lane<3){
    float v = (lane==0)?cx:((lane==1)?cy:cz);
    g_new_xyz[gw*3+lane]=v;
    out[(size_t)b*3*SPTS + (size_t)lane*SPTS + s]=v;
  }
  unsigned cnt=0;
  for (int basep=0; basep<NPTS; basep+=32){
    int pp = basep+lane;
    float dx=__fsub_rn(cx,xb[pp]);
    float dy=__fsub_rn(cy,xb[NPTS+pp]);
    float dz=__fsub_rn(cz,xb[2*NPTS+pp]);
    float d=__fadd_rn(__fadd_rn(__fmul_rn(dx,dx),__fmul_rn(dy,dy)),__fmul_rn(dz,dz));
    bool in = !(d > 0.04f);
    unsigned mm = __ballot_sync(0xffffffffu, in);
    if (in){
      unsigned r = cnt + __popc(mm & ((1u<<lane)-1u));
      if (r < NS) sidx[wl][r] = pp;
    }
    cnt += __popc(mm);
    if (cnt >= NS) break;
  }
  __syncwarp();
  unsigned c = cnt < NS ? cnt : NS;
  int first = sidx[wl][0];
  int v = (lane < (int)c) ? sidx[wl][lane] : first;
  g_ball[gw*NS + lane] = v;
}

// ---------------- points transpose (B,64,N) -> (B,N,64) --------------------
__global__ void transpose_kernel(const float* __restrict__ pts){
  __shared__ float tile[32][33];
  int b  = blockIdx.z;
  int n0 = blockIdx.x*32;
  int c0 = blockIdx.y*32;
  int tx = threadIdx.x, ty = threadIdx.y;     // 32 x 8
  const float* pb = pts + (size_t)b*DIM*NPTS;
#pragma unroll
  for (int j=0;j<32;j+=8)
    tile[ty+j][tx] = pb[(size_t)(c0+ty+j)*NPTS + n0+tx];
  __syncthreads();
  float* ob = g_ptsT + (size_t)b*NPTS*DIM;
#pragma unroll
  for (int j=0;j<32;j+=8)
    ob[(size_t)(n0+ty+j)*DIM + c0+tx] = tile[tx][ty+j];
}

// ---------------- GEMM: 128-row tile, 8x8 thread tile, split columns -------
// T = 2*BN threads. tm = tid/TN (0..15) owns rows tm*8..+7 (A = 2x LDS.128).
// tn = tid%TN owns cols {tn*4..+3} and {BN/2+tn*4..+3} (B = 2x LDS.128,
// conflict-free per 8-lane phase: word addr 4*tn mod 32 distinct).
// MODE 0: layer1 — gather A from ptsT/ball/xyz (K=68, wld=67)
// MODE 1: layer2 — A = prev H with fused BN+ReLU (K=64)
// MODE 2: layer3 — no H store, + max/min pool epilogue (BN=128)
template<int K, int BN, int MODE, int UNR>
__global__ __launch_bounds__(2*BN) void gemm_kernel(const float* __restrict__ A,
    const float* __restrict__ W, int wld,
    const float* __restrict__ bias, float* __restrict__ H,
    const float* __restrict__ xyz){
  constexpr bool GATHER = (MODE==0);
  constexpr bool AFF    = (MODE>=1);
  constexpr bool POOL   = (MODE==2);
  constexpr int  T  = 2*BN;             // 128 or 256 threads
  constexpr int  TN = BN/8;             // 8 or 16
  constexpr int  CH = BN/2;             // split-column offset
  extern __shared__ float sm[];
  float* sAT   = sm;                    // [K][AST]  K-major A tile (128 rows)
  float* sB    = sAT + K*AST;           // [K][BN+4]
  float* sbias = sB + K*(BN+4);         // BN
  float* ssc   = sbias + BN;            // K (AFF only)
  float* ssh   = ssc + K;
  __shared__ int   sn[128];
  __shared__ float sctr[12];
  const int tid = threadIdx.x;
  const int m0  = blockIdx.x*128;

  for (int o=tid;o<BN;o+=T) sbias[o]=bias[o];
  if (AFF) for (int cc=tid; cc<K; cc+=T){ ssc[cc]=g_scale[cc]; ssh[cc]=g_shift[cc]; }
  for (int idx=tid; idx<BN*wld; idx+=T){
    int o=idx/wld, cc=idx-o*wld;
    sB[cc*(BN+4)+o]=W[idx];
  }
  if (K>wld) for (int o=tid;o<BN;o+=T) sB[(K-1)*(BN+4)+o]=0.f;

  if (GATHER){
    if (tid<128) sn[tid] = g_ball[(size_t)m0 + tid];
    if (tid<12)  sctr[tid] = g_new_xyz[(m0>>5)*3 + tid];
    __syncthreads();
    const int b = blockIdx.x >> 8;      // 256 blocks per batch
    for (int idx=tid; idx<128*16; idx+=T){
      int c4 = idx >> 7;                // 0..15
      int m  = idx & 127;               // 0..127
      int n  = sn[m];
      float4 v = *(const float4*)(g_ptsT + ((size_t)b*NPTS + n)*DIM + c4*4);
      int cc=3+c4*4;
      sAT[(cc  )*AST+m]=v.x;
      sAT[(cc+1)*AST+m]=v.y;
      sAT[(cc+2)*AST+m]=v.z;
      sAT[(cc+3)*AST+m]=v.w;
    }
    if (tid<128){
      int n=sn[tid];
      const float* xb = xyz + (size_t)b*3*NPTS;
      const int grp = (tid>>5)*3;
      sAT[0*AST+tid] = __fsub_rn(xb[n],        sctr[grp+0]);
      sAT[1*AST+tid] = __fsub_rn(xb[NPTS+n],   sctr[grp+1]);
      sAT[2*AST+tid] = __fsub_rn(xb[2*NPTS+n], sctr[grp+2]);
      sAT[67*AST+tid]= 0.f;
    }
  } else {
    __syncthreads();                    // ssc/ssh visible
    constexpr int K4 = K/4;
    const float4* A4 = (const float4*)A;
    for (int idx=tid; idx<128*K4; idx+=T){
      int m=idx>>4, c4=idx&15;          // K4==16 for MODE>=1
      float4 v = A4[(size_t)(m0+m)*K4 + c4];
      int cc=c4*4;
      v.x = fmaxf(fmaf(v.x, ssc[cc  ], ssh[cc  ]), 0.f);
      v.y = fmaxf(fmaf(v.y, ssc[cc+1], ssh[cc+1]), 0.f);
      v.z = fmaxf(fmaf(v.z, ssc[cc+2], ssh[cc+2]), 0.f);
      v.w = fmaxf(fmaf(v.w, ssc[cc+3], ssh[cc+3]), 0.f);
      sAT[(cc  )*AST+m]=v.x;
      sAT[(cc+1)*AST+m]=v.y;
      sAT[(cc+2)*AST+m]=v.z;
      sAT[(cc+3)*AST+m]=v.w;
    }
  }
  __syncthreads();

  // ---- main loop: 8 rows x 8 cols per thread (split columns) ----
  const int tm = tid/TN, tn = tid%TN;
  u64 acc[8][4];
#pragma unroll
  for (int i=0;i<8;i++){
    acc[i][0]=pack2(sbias[tn*4   ], sbias[tn*4+1   ]);
    acc[i][1]=pack2(sbias[tn*4+2 ], sbias[tn*4+3   ]);
    acc[i][2]=pack2(sbias[CH+tn*4], sbias[CH+tn*4+1]);
    acc[i][3]=pack2(sbias[CH+tn*4+2], sbias[CH+tn*4+3]);
  }

  const float* ApT = sAT + tm*8;
  const float* Bp  = sB + tn*4;
#pragma unroll UNR
  for (int k=0;k<K;k++){
    float4 av0 = *(const float4*)(ApT + k*AST);      // rows 0..3
    float4 av1 = *(const float4*)(ApT + k*AST + 4);  // rows 4..7
    u64 a[8];
    a[0]=pack2(av0.x,av0.x); a[1]=pack2(av0.y,av0.y);
    a[2]=pack2(av0.z,av0.z); a[3]=pack2(av0.w,av0.w);
    a[4]=pack2(av1.x,av1.x); a[5]=pack2(av1.y,av1.y);
    a[6]=pack2(av1.z,av1.z); a[7]=pack2(av1.w,av1.w);
    float4 t0 = *(const float4*)(Bp + k*(BN+4));
    float4 t1 = *(const float4*)(Bp + k*(BN+4) + CH);
    u64 b2[4];
    b2[0]=pack2(t0.x,t0.y); b2[1]=pack2(t0.z,t0.w);
    b2[2]=pack2(t1.x,t1.y); b2[3]=pack2(t1.z,t1.w);
#pragma unroll
    for (int i=0;i<8;i++)
#pragma unroll
      for (int j=0;j<4;j++)
        fma2(acc[i][j],a[i],b2[j]);
  }

  float vals[8][8];                     // j: 0..3 -> cols tn*4+j ; 4..7 -> CH+tn*4+(j-4)
#pragma unroll
  for (int i=0;i<8;i++)
#pragma unroll
    for (int j=0;j<4;j++) unpack2(vals[i][2*j], vals[i][2*j+1], acc[i][j]);

  if (!POOL){
#pragma unroll
    for (int i=0;i<8;i++){
      float* outp = H + (size_t)(m0+tm*8+i)*BN + tn*4;
      float4 t0; t0.x=vals[i][0]; t0.y=vals[i][1]; t0.z=vals[i][2]; t0.w=vals[i][3];
      float4 t1; t1.x=vals[i][4]; t1.y=vals[i][5]; t1.z=vals[i][6]; t1.w=vals[i][7];
      *(float4*)(outp)      = t0;
      *(float4*)(outp + CH) = t1;
    }
  }

  // ---- deterministic column sum / sumsq ----
  __syncthreads();
  float* sS  = sm;                      // [BN][16]
  float* sSS = sm + 16*BN;              // [BN][16]
#pragma unroll
  for (int j=0;j<8;j++){
    int col = (j<4) ? (tn*4+j) : (CH+tn*4+j-4);
    float s=0.f, ss=0.f;
#pragma unroll
    for (int i=0;i<8;i++){ float v=vals[i][j]; s+=v; ss+=v*v; }
    sS [col*16 + tm] = s;
    sSS[col*16 + tm] = ss;
  }
  __syncthreads();
  if (tid < BN){
    float s=0.f, ss=0.f;
#pragma unroll
    for (int t=0;t<16;t++){ s+=sS[tid*16+t]; ss+=sSS[tid*16+t]; }
    g_pS [(size_t)tid*NBLK + blockIdx.x] = s;
    g_pSS[(size_t)tid*NBLK + blockIdx.x] = ss;
  }

  if (POOL){
    // rows tm*8..tm*8+7 all lie in sample group tm>>2 (32 rows per sample)
    __syncthreads();
#pragma unroll
    for (int j=0;j<8;j++){
      int col = (j<4) ? (tn*4+j) : (CH+tn*4+j-4);
      float mx=-3.4e38f, mn=3.4e38f;
#pragma unroll
      for (int i=0;i<8;i++){ mx=fmaxf(mx,vals[i][j]); mn=fminf(mn,vals[i][j]); }
      sS [col*16 + tm] = mx;
      sSS[col*16 + tm] = mn;
    }
    __syncthreads();
    // 4 sample groups x 128 cols = 512 outputs
    for (int it=tid; it<4*128; it+=T){
      int grp = it>>7, col = it&127;
      float mx=-3.4e38f, mn=3.4e38f;
#pragma unroll
      for (int t=0;t<4;t++){
        mx = fmaxf(mx, sS [col*16 + grp*4 + t]);
        mn = fminf(mn, sSS[col*16 + grp*4 + t]);
      }
      size_t gidx = (size_t)(blockIdx.x*4+grp)*128 + col;
      g_mx[gidx]=mx; g_mn[gidx]=mn;
    }
  }
}

// ---------------- BN stats (+ optional fused final pool output) -------------
template<bool POOLOUT>
__global__ void bnstats_kernel(const float* __restrict__ g, const float* __restrict__ beta,
                               float* __restrict__ out){
  __shared__ float sh[512];
  __shared__ float sscsh[2];
  const int c=blockIdx.x, t=threadIdx.x;   // 256 threads
  float s=0.f, ss=0.f;
  const float* ps  = g_pS  + (size_t)c*NBLK;
  const float* pss = g_pSS + (size_t)c*NBLK;
  for (int i=t;i<NBLK;i+=256){ s+=ps[i]; ss+=pss[i]; }
  sh[t]=s; sh[256+t]=ss; __syncthreads();
  for (int o=128;o>0;o>>=1){
    if (t<o){ sh[t]+=sh[t+o]; sh[256+t]+=sh[256+t+o]; }
    __syncthreads();
  }
  if (t==0){
    const float inv = 1.0f/(float)MROWS;
    float mean = sh[0]*inv;
    float var  = sh[256]*inv - mean*mean;
    float rstd = rsqrtf(var + 1e-5f);
    float sc   = rstd*g[c];
    float shv  = beta[c] - mean*sc;
    g_scale[c] = sc;
    g_shift[c] = shv;
    sscsh[0]=sc; sscsh[1]=shv;
  }
  if (POOLOUT){
    __syncthreads();
    const float sc = sscsh[0], shv = sscsh[1];
    const bool pos = (sc>=0.f);
    for (int gq=t; gq<BATCH*SPTS; gq+=256){
      float mv = pos ? g_mx[(size_t)gq*128+c] : g_mn[(size_t)gq*128+c];
      float v  = fmaf(mv, sc, shv);
      int b = gq>>10, sq = gq&1023;
      out[24576 + (size_t)b*131072 + (size_t)c*1024 + sq] = fmaxf(v, 0.f);
    }
  }
}

// ---------------- launch ----------------------------------------------------
extern "C" void kernel_launch(void* const* d_in, const int* in_sizes, int n_in,
                              void* d_out, int out_size){
  (void)in_sizes; (void)n_in; (void)out_size;
  const float* xyz = (const float*)d_in[0];
  const float* pts = (const float*)d_in[1];
  const float* w0  = (const float*)d_in[2];
  const float* b0  = (const float*)d_in[3];
  const float* gg0 = (const float*)d_in[4];
  const float* be0 = (const float*)d_in[5];
  const float* w1  = (const float*)d_in[6];
  const float* b1  = (const float*)d_in[7];
  const float* gg1 = (const float*)d_in[8];
  const float* be1 = (const float*)d_in[9];
  const float* w2  = (const float*)d_in[10];
  const float* b2  = (const float*)d_in[11];
  const float* gg2 = (const float*)d_in[12];
  const float* be2 = (const float*)d_in[13];
  float* out = (float*)d_out;

  // smem (floats): K*AST + K*(BN+4) + BN + 2*K (AFF)
  const int smem1 = (68*AST + 68*68 + 64)*4;            // 54656
  const int smem2 = (64*AST + 64*68 + 64 + 128)*4;      // 52480
  const int smem3 = (64*AST + 64*132 + 128 + 128)*4;    // 68608

  cudaFuncSetAttribute(fps_kernel, cudaFuncAttributeMaxDynamicSharedMemorySize, 3*NPTS*4);
  cudaFuncSetAttribute((const void*)gemm_kernel<68,64,0,4>,
                       cudaFuncAttributeMaxDynamicSharedMemorySize, smem1);
  cudaFuncSetAttribute((const void*)gemm_kernel<64,64,1,4>,
                       cudaFuncAttributeMaxDynamicSharedMemorySize, smem2);
  cudaFuncSetAttribute((const void*)gemm_kernel<64,128,2,2>,
                       cudaFuncAttributeMaxDynamicSharedMemorySize, smem3);

  float *pH1,*pH2;
  cudaGetSymbolAddress((void**)&pH1, g_h1);
  cudaGetSymbolAddress((void**)&pH2, g_h2);

  fps_kernel<<<BATCH, 1024, 3*NPTS*4>>>(xyz);
  ball_kernel<<<1024, 256>>>(xyz, out);
  transpose_kernel<<<dim3(NPTS/32, DIM/32, BATCH), dim3(32,8)>>>(pts);

  gemm_kernel<68,64,0,4><<<NBLK, 128, smem1>>>(nullptr, w0, 67, b0, pH1, xyz);
  bnstats_kernel<false><<<64, 256>>>(gg0, be0, nullptr);

  gemm_kernel<64,64,1,4><<<NBLK, 128, smem2>>>(pH1, w1, 64, b1, pH2, xyz);
  bnstats_kernel<false><<<64, 256>>>(gg1, be1, nullptr);

  gemm_kernel<64,128,2,2><<<NBLK, 256, smem3>>>(pH2, w2, 64, b2, nullptr, xyz);
  bnstats_kernel<true><<<128, 256>>>(gg2, be2, out);
}